// round 1
// baseline (speedup 1.0000x reference)
#include <cuda_runtime.h>
#include <math.h>

// ---------------- problem constants ----------------
#define Bsz 1024
#define Kn  20
#define DN  172
#define DE  172
#define DT  100
#define NHh 2
#define QD  272       // DN + DT
#define KDd 444       // DN + DE + DT
#define HDd 136       // QD / NH
#define M2  (Bsz*Kn)  // 20480
#define MK2 (M2*Kn)   // 409600

// ---------------- device scratch (static; no allocations allowed) ----------------
__device__ __align__(16) float g_nf[M2*DN];
__device__ __align__(16) float g_qin[M2*QD];
__device__ __align__(16) float g_q[M2*QD];
__device__ __align__(16) float g_att[M2*QD];
__device__ __align__(16) float g_o[M2*QD];
__device__ __align__(16) float g_x[M2*QD];
__device__ __align__(16) float g_cat[M2*(QD+DN)];
__device__ __align__(16) float g_h[M2*DN];
__device__ __align__(16) float g_nbrconv[M2*DN];
__device__ __align__(16) float g_nodeconv[Bsz*DN];
__device__ __align__(16) float g_kv[(size_t)MK2*KDd];
__device__ __align__(16) float g_k[(size_t)MK2*QD];
__device__ __align__(16) float g_v[(size_t)MK2*QD];

// ---------------- packed f32x2 helpers (sm_100+) ----------------
__device__ __forceinline__ unsigned long long pack2(float x, float y) {
    unsigned long long r;
    asm("mov.b64 %0, {%1,%2};" : "=l"(r) : "f"(x), "f"(y));
    return r;
}
__device__ __forceinline__ unsigned long long fma2(unsigned long long a,
                                                   unsigned long long b,
                                                   unsigned long long c) {
    unsigned long long d;
    asm("fma.rn.f32x2 %0, %1, %2, %3;" : "=l"(d) : "l"(a), "l"(b), "l"(c));
    return d;
}
__device__ __forceinline__ void unpack2(unsigned long long p, float& x, float& y) {
    asm("mov.b64 {%0,%1}, %2;" : "=f"(x), "=f"(y) : "l"(p));
}

// ---------------- GEMM: C[M,N] = A[M,Kd] @ W[Kd,N] (+bias)(+relu) ----------------
// 128x64 tile, BK=16, 256 threads, 8x4 per-thread microtile via fma.rn.f32x2.
#define BM 128
#define BN 64
#define BK 16

__global__ void __launch_bounds__(256) gemm_kernel(
    const float* __restrict__ A, const float* __restrict__ W,
    const float* __restrict__ bias, float* __restrict__ C,
    int M, int Kd, int N, int epi)   // epi: 0=none, 1=bias, 2=bias+relu
{
    __shared__ __align__(16) float As[BK][BM + 4];  // transposed A tile
    __shared__ __align__(16) float Ws[BK][BN];

    const int tid = threadIdx.x;
    const int tr = tid >> 4;    // 0..15, 8 rows each
    const int tc = tid & 15;    // 0..15, 4 cols each
    const int m0 = blockIdx.y * BM;
    const int n0 = blockIdx.x * BN;

    unsigned long long accp[4][4];
#pragma unroll
    for (int i = 0; i < 4; i++)
#pragma unroll
        for (int j = 0; j < 4; j++) accp[i][j] = 0ull;

    for (int k0 = 0; k0 < Kd; k0 += BK) {
        // load A tile 128x16 (512 float4s / 256 threads = 2 each), store transposed
#pragma unroll
        for (int i = 0; i < 2; i++) {
            int f = tid + i * 256;
            int row = f >> 2;
            int c4 = (f & 3) << 2;
            float4 a = make_float4(0.f, 0.f, 0.f, 0.f);
            int gr = m0 + row, gc = k0 + c4;
            if (gr < M && gc < Kd)
                a = *(const float4*)(A + (size_t)gr * Kd + gc);
            As[c4 + 0][row] = a.x;
            As[c4 + 1][row] = a.y;
            As[c4 + 2][row] = a.z;
            As[c4 + 3][row] = a.w;
        }
        // load W tile 16x64 (1 float4 per thread)
        {
            int row = tid >> 4;
            int c4 = (tid & 15) << 2;
            float4 w = make_float4(0.f, 0.f, 0.f, 0.f);
            int gr = k0 + row, gc = n0 + c4;
            if (gr < Kd && gc < N)
                w = *(const float4*)(W + (size_t)gr * N + gc);
            *(float4*)&Ws[row][c4] = w;
        }
        __syncthreads();
#pragma unroll
        for (int kk = 0; kk < BK; kk++) {
            float4 w4 = *(const float4*)&Ws[kk][tc << 2];
            unsigned long long w2[4];
            w2[0] = pack2(w4.x, w4.x);
            w2[1] = pack2(w4.y, w4.y);
            w2[2] = pack2(w4.z, w4.z);
            w2[3] = pack2(w4.w, w4.w);
            const unsigned long long* ap =
                (const unsigned long long*)&As[kk][tr << 3];
#pragma unroll
            for (int i = 0; i < 4; i++) {
                unsigned long long a2 = ap[i];
                accp[i][0] = fma2(a2, w2[0], accp[i][0]);
                accp[i][1] = fma2(a2, w2[1], accp[i][1]);
                accp[i][2] = fma2(a2, w2[2], accp[i][2]);
                accp[i][3] = fma2(a2, w2[3], accp[i][3]);
            }
        }
        __syncthreads();
    }
    // epilogue
#pragma unroll
    for (int i = 0; i < 4; i++) {
#pragma unroll
        for (int j = 0; j < 4; j++) {
            float lo, hi;
            unpack2(accp[i][j], lo, hi);
            int gn = n0 + (tc << 2) + j;
            if (gn >= N) continue;
            float b = (epi >= 1) ? bias[gn] : 0.f;
            float v0 = lo + b, v1 = hi + b;
            if (epi == 2) { v0 = fmaxf(v0, 0.f); v1 = fmaxf(v1, 0.f); }
            int r0 = m0 + (tr << 3) + 2 * i;
            if (r0 < M)     C[(size_t)r0 * N + gn] = v0;
            if (r0 + 1 < M) C[(size_t)(r0 + 1) * N + gn] = v1;
        }
    }
}

// ---------------- feature-build kernels ----------------
__global__ void build_nf_qin(const int* __restrict__ ids,
                             const float* __restrict__ memories,
                             const float* __restrict__ node_raw,
                             const float* __restrict__ time_b,
                             float* __restrict__ nf, float* __restrict__ qin, int M)
{
    int m = blockIdx.x;
    int id = ids[m];
    for (int j = threadIdx.x; j < QD; j += blockDim.x) {
        if (j < DN) {
            float v = memories[(size_t)id * DN + j] + node_raw[(size_t)id * DN + j];
            nf[(size_t)m * DN + j] = v;
            qin[(size_t)m * QD + j] = v;
        } else {
            // time_encode(0): cos(0*w + b) = cos(b)
            qin[(size_t)m * QD + j] = cosf(time_b[j - DN]);
        }
    }
}

__global__ void build_qin_conv(const float* __restrict__ conv,
                               const float* __restrict__ time_b,
                               float* __restrict__ qin, int M)
{
    int m = blockIdx.x;
    for (int j = threadIdx.x; j < QD; j += blockDim.x)
        qin[(size_t)m * QD + j] =
            (j < DN) ? conv[(size_t)m * DN + j] : cosf(time_b[j - DN]);
}

// kv_in row r=(m,kk): [ node feat (DN) | edge feat (DE) | time feat (DT) ]
__global__ void build_kv(const float* __restrict__ nbr_feat,  // null -> gather tables
                         const int* __restrict__ nbr_ids,
                         const int* __restrict__ nbr_eids,
                         const float* __restrict__ times,
                         const float* __restrict__ nbr_times,
                         const float* __restrict__ memories,
                         const float* __restrict__ node_raw,
                         const float* __restrict__ edge_raw,
                         const float* __restrict__ time_w,
                         const float* __restrict__ time_b,
                         float* __restrict__ kv, int MK)
{
    int r = blockIdx.x;
    int m = r / Kn;
    int nid = nbr_ids[r];
    int eid = nbr_eids[r];
    // plain fp32 subtract (matches jax; no fma contraction anywhere below)
    float dt = __fadd_rn(times[m], -nbr_times[r]);
    float* dst = kv + (size_t)r * KDd;
    for (int j = threadIdx.x; j < KDd; j += blockDim.x) {
        float v;
        if (j < DN) {
            v = nbr_feat ? nbr_feat[(size_t)r * DN + j]
                         : memories[(size_t)nid * DN + j] + node_raw[(size_t)nid * DN + j];
        } else if (j < DN + DE) {
            v = edge_raw[(size_t)eid * DE + (j - DN)];
        } else {
            int jj = j - DN - DE;
            float arg = __fadd_rn(__fmul_rn(dt, time_w[jj]), time_b[jj]);
            v = cosf(arg);
        }
        dst[j] = v;
    }
}

// ---------------- attention (1 query vs K keys, NH=2 heads) ----------------
__global__ void attention_kernel(const float* __restrict__ q,
                                 const float* __restrict__ k,
                                 const float* __restrict__ v,
                                 const int* __restrict__ nbr_ids,
                                 float* __restrict__ out, int M)
{
    const float SCALE = 0.08574929257125442f;  // 136^-0.5
    int m = blockIdx.x;
    int tid = threadIdx.x;  // 256
    __shared__ float qs[QD];
    __shared__ float att[NHh * Kn];

    for (int j = tid; j < QD; j += 256) qs[j] = q[(size_t)m * QD + j];
    __syncthreads();

    int warp = tid >> 5, lane = tid & 31;
    for (int p = warp; p < NHh * Kn; p += 8) {
        int h = p / Kn, kk = p % Kn;
        const float* krow = k + ((size_t)m * Kn + kk) * QD + h * HDd;
        const float* qrow = qs + h * HDd;
        float s = 0.f;
        for (int d = lane; d < HDd; d += 32) s += qrow[d] * krow[d];
#pragma unroll
        for (int o = 16; o; o >>= 1) s += __shfl_xor_sync(0xffffffffu, s, o);
        if (lane == 0) {
            if (nbr_ids[(size_t)m * Kn + kk] == 0) s = -1e10f;
            else s *= SCALE;
            att[p] = s;
        }
    }
    __syncthreads();

    if (tid < NHh) {
        int h = tid;
        float mx = -INFINITY;
        for (int kk = 0; kk < Kn; kk++) mx = fmaxf(mx, att[h * Kn + kk]);
        float sum = 0.f;
        for (int kk = 0; kk < Kn; kk++) {
            float e = expf(att[h * Kn + kk] - mx);
            att[h * Kn + kk] = e;
            sum += e;
        }
        float inv = 1.f / sum;
        for (int kk = 0; kk < Kn; kk++) att[h * Kn + kk] *= inv;
    }
    __syncthreads();

    for (int j = tid; j < QD; j += 256) {
        int h = j / HDd;
        float acc = 0.f;
        for (int kk = 0; kk < Kn; kk++)
            acc += att[h * Kn + kk] * v[((size_t)m * Kn + kk) * QD + j];
        out[(size_t)m * QD + j] = acc;
    }
}

// ---------------- residual + bias + LayerNorm ----------------
__global__ void ln_kernel(const float* __restrict__ o, const float* __restrict__ bo,
                          const float* __restrict__ qin, const float* __restrict__ gam,
                          const float* __restrict__ bet, float* __restrict__ x, int M)
{
    int m = blockIdx.x;
    int tid = threadIdx.x;  // 256
    __shared__ float buf[QD];
    __shared__ float red[32];

    for (int j = tid; j < QD; j += 256)
        buf[j] = o[(size_t)m * QD + j] + bo[j] + qin[(size_t)m * QD + j];
    __syncthreads();

    float s = 0.f;
    for (int j = tid; j < QD; j += 256) s += buf[j];
#pragma unroll
    for (int off = 16; off; off >>= 1) s += __shfl_xor_sync(0xffffffffu, s, off);
    if ((tid & 31) == 0) red[tid >> 5] = s;
    __syncthreads();
    if (tid < 32) {
        float t = (tid < 8) ? red[tid] : 0.f;
#pragma unroll
        for (int off = 4; off; off >>= 1) t += __shfl_xor_sync(0xffffffffu, t, off);
        if (tid == 0) red[0] = t;
    }
    __syncthreads();
    float mu = red[0] / (float)QD;
    __syncthreads();

    float s2 = 0.f;
    for (int j = tid; j < QD; j += 256) {
        float d = buf[j] - mu;
        s2 += d * d;
    }
#pragma unroll
    for (int off = 16; off; off >>= 1) s2 += __shfl_xor_sync(0xffffffffu, s2, off);
    if ((tid & 31) == 0) red[tid >> 5] = s2;
    __syncthreads();
    if (tid < 32) {
        float t = (tid < 8) ? red[tid] : 0.f;
#pragma unroll
        for (int off = 4; off; off >>= 1) t += __shfl_xor_sync(0xffffffffu, t, off);
        if (tid == 0) red[0] = t;
    }
    __syncthreads();
    float var = red[0] / (float)QD;
    float rinv = 1.0f / sqrtf(var + 1e-5f);
    for (int j = tid; j < QD; j += 256)
        x[(size_t)m * QD + j] = (buf[j] - mu) * rinv * gam[j] + bet[j];
}

__global__ void build_cat(const float* __restrict__ x, const float* __restrict__ nf,
                          float* __restrict__ cat, int M)
{
    int m = blockIdx.x;
    for (int j = threadIdx.x; j < QD + DN; j += blockDim.x)
        cat[(size_t)m * (QD + DN) + j] =
            (j < QD) ? x[(size_t)m * QD + j] : nf[(size_t)m * DN + (j - QD)];
}

// ---------------- host orchestration ----------------
extern "C" void kernel_launch(void* const* d_in, const int* in_sizes, int n_in,
                              void* d_out, int out_size)
{
    (void)in_sizes; (void)n_in; (void)out_size;
    const float* node_raw = (const float*)d_in[0];
    const float* edge_raw = (const float*)d_in[1];
    const float* memories = (const float*)d_in[2];
    const float* t_node   = (const float*)d_in[3];
    const float* t_n1     = (const float*)d_in[4];
    const float* t_n2     = (const float*)d_in[5];
    const float* time_w   = (const float*)d_in[6];
    const float* time_b   = (const float*)d_in[7];
    const float* Wq       = (const float*)d_in[8];
    const float* Wk       = (const float*)d_in[9];
    const float* Wv       = (const float*)d_in[10];
    const float* Wo       = (const float*)d_in[11];
    const float* bo       = (const float*)d_in[12];
    const float* ln_g     = (const float*)d_in[13];
    const float* ln_b     = (const float*)d_in[14];
    const float* m_w1     = (const float*)d_in[15];
    const float* m_b1     = (const float*)d_in[16];
    const float* m_w2     = (const float*)d_in[17];
    const float* m_b2     = (const float*)d_in[18];
    const int* node_ids   = (const int*)d_in[19];
    const int* n1_ids     = (const int*)d_in[20];
    const int* n1_eids    = (const int*)d_in[21];
    const int* n2_ids     = (const int*)d_in[22];
    const int* n2_eids    = (const int*)d_in[23];
    float* out = (float*)d_out;

    float *nf, *qin, *q, *att, *o, *x, *cat, *h, *nbrconv, *nodeconv, *kv, *k, *v;
    cudaGetSymbolAddress((void**)&nf, g_nf);
    cudaGetSymbolAddress((void**)&qin, g_qin);
    cudaGetSymbolAddress((void**)&q, g_q);
    cudaGetSymbolAddress((void**)&att, g_att);
    cudaGetSymbolAddress((void**)&o, g_o);
    cudaGetSymbolAddress((void**)&x, g_x);
    cudaGetSymbolAddress((void**)&cat, g_cat);
    cudaGetSymbolAddress((void**)&h, g_h);
    cudaGetSymbolAddress((void**)&nbrconv, g_nbrconv);
    cudaGetSymbolAddress((void**)&nodeconv, g_nodeconv);
    cudaGetSymbolAddress((void**)&kv, g_kv);
    cudaGetSymbolAddress((void**)&k, g_k);
    cudaGetSymbolAddress((void**)&v, g_v);

    auto gemm = [&](const float* A, const float* W, const float* bias, float* C,
                    int M, int Kd, int N, int epi) {
        dim3 grid((N + BN - 1) / BN, (M + BM - 1) / BM);
        gemm_kernel<<<grid, 256>>>(A, W, bias, C, M, Kd, N, epi);
    };

    // common tail of one temporal layer (kv, qin, nf already built)
    auto layer_tail = [&](int M, const int* nbrids, int l, float* outbuf) {
        int MK = M * Kn;
        gemm(qin, Wq + (size_t)l * QD * QD, nullptr, q, M, QD, QD, 0);
        gemm(kv, Wk + (size_t)l * KDd * QD, nullptr, k, MK, KDd, QD, 0);
        gemm(kv, Wv + (size_t)l * KDd * QD, nullptr, v, MK, KDd, QD, 0);
        attention_kernel<<<M, 256>>>(q, k, v, nbrids, att, M);
        gemm(att, Wo + (size_t)l * QD * QD, nullptr, o, M, QD, QD, 0);
        ln_kernel<<<M, 256>>>(o, bo + (size_t)l * QD, qin,
                              ln_g + (size_t)l * QD, ln_b + (size_t)l * QD, x, M);
        build_cat<<<M, 256>>>(x, nf, cat, M);
        gemm(cat, m_w1 + (size_t)l * (QD + DN) * DN, m_b1 + (size_t)l * DN, h,
             M, QD + DN, DN, 2);
        gemm(h, m_w2 + (size_t)l * DN * DN, m_b2 + (size_t)l * DN, outbuf,
             M, DN, DN, 1);
    };

    // Phase A: layer-1 over all (B*K) first-hop neighbors -> g_nbrconv
    build_nf_qin<<<M2, 256>>>(n1_ids, memories, node_raw, time_b, nf, qin, M2);
    build_kv<<<MK2, 256>>>(nullptr, n2_ids, n2_eids, t_n1, t_n2,
                           memories, node_raw, edge_raw, time_w, time_b, kv, MK2);
    layer_tail(M2, n2_ids, 0, nbrconv);

    // Phase B: layer-1 over the B center nodes -> g_nodeconv (g_nf now = node nf)
    build_nf_qin<<<Bsz, 256>>>(node_ids, memories, node_raw, time_b, nf, qin, Bsz);
    build_kv<<<Bsz * Kn, 256>>>(nullptr, n1_ids, n1_eids, t_node, t_n1,
                                memories, node_raw, edge_raw, time_w, time_b,
                                kv, Bsz * Kn);
    layer_tail(Bsz, n1_ids, 0, nodeconv);

    // Phase C: layer 2 (queries = nodeconv, keys/values use nbrconv); g_nf still
    // holds memories[node_ids]+node_raw[node_ids] from phase B (layer-2 residual nf).
    build_qin_conv<<<Bsz, 256>>>(nodeconv, time_b, qin, Bsz);
    build_kv<<<Bsz * Kn, 256>>>(nbrconv, n1_ids, n1_eids, t_node, t_n1,
                                memories, node_raw, edge_raw, time_w, time_b,
                                kv, Bsz * Kn);
    layer_tail(Bsz, n1_ids, 1, out);
}